// round 3
// baseline (speedup 1.0000x reference)
#include <cuda_runtime.h>

// Segmented GroupNorm: N rows x C=64 channels, G=32 groups (Cg=2), S=100 instances.
//
//   k0 zero:  clear global scratch
//   k1 pass1: per-(seg,group) sum/sumsq + per-seg counts; per-warp-private
//             shared tables, float4 loads (warp = 2 rows/step), software-
//             pipelined, contiguous per-warp row-pair chunks. Same-seg row
//             pairs are combined via shfl to avoid lost-update races.
//   k2 stats: (mean, inv_std) per (seg,group)
//   k3 pass3: normalize with float4 loads/stores (warp = 2 rows/step)

#define C_     64
#define G_     32
#define S_MAX  1024
#define S_SH   104      // shared-privatized capacity per warp (dataset S=100)
#define EPS_   1e-5f

__device__ float2 g_s12[S_MAX * G_];   // (sum, sumsq) per (seg, group)
__device__ float  g_cnt[S_MAX];        // rows per seg
__device__ float2 g_stat[S_MAX * G_];  // (mean, inv_std) per (seg, group)

// ---------------- k0: zero scratch ----------------
__global__ void zero_kernel() {
    int i = blockIdx.x * blockDim.x + threadIdx.x;
    if (i < S_MAX * G_) g_s12[i] = make_float2(0.f, 0.f);
    if (i < S_MAX)      g_cnt[i] = 0.f;
}

// ---------------- k1: segmented sums (pipelined, float4) ----------------
#define W1 4     // warps per block
#define U1 8     // row-pairs per batch per warp

extern __shared__ unsigned char smem_raw[];
// layout: float4 acc[W1][S_SH*16]  then  float cnt[W1][S_SH]
#define ACC_F4_PER_WARP (S_SH * 16)

__device__ __forceinline__ void global_fallback(int s, float s1a, float s2a,
                                                float s1b, float s2b, int q) {
    if ((unsigned)s < S_MAX) {
        atomicAdd(&g_s12[s * G_ + 2 * q].x,     s1a);
        atomicAdd(&g_s12[s * G_ + 2 * q].y,     s2a);
        atomicAdd(&g_s12[s * G_ + 2 * q + 1].x, s1b);
        atomicAdd(&g_s12[s * G_ + 2 * q + 1].y, s2b);
    }
}

// process one row-pair for this warp. v = this lane's float4 (channels 4q..4q+3
// of row 2p+h), s = seg of this lane's row (uniform per half-warp).
__device__ __forceinline__ void process_pair(float4* acc4, float* cnt,
                                             int lane, int q, int h,
                                             int s, float4 v) {
    float s1a = v.x + v.y;                       // group 2q
    float s2a = fmaf(v.x, v.x, v.y * v.y);
    float s1b = v.z + v.w;                       // group 2q+1
    float s2b = fmaf(v.z, v.z, v.w * v.w);

    int sO = __shfl_xor_sync(0xffffffffu, s, 16);
    if (s == sO) {                               // warp-uniform branch
        // combine both rows; only lanes < 16 write (avoids lost update)
        s1a += __shfl_xor_sync(0xffffffffu, s1a, 16);
        s2a += __shfl_xor_sync(0xffffffffu, s2a, 16);
        s1b += __shfl_xor_sync(0xffffffffu, s1b, 16);
        s2b += __shfl_xor_sync(0xffffffffu, s2b, 16);
        if (h == 0) {
            if ((unsigned)s < S_SH) {
                float4 a = acc4[s * 16 + q];
                a.x += s1a; a.y += s2a; a.z += s1b; a.w += s2b;
                acc4[s * 16 + q] = a;
                if (lane == 0) cnt[s] += 2.f;
            } else {
                global_fallback(s, s1a, s2a, s1b, s2b, q);
                if (lane == 0 && (unsigned)s < S_MAX) atomicAdd(&g_cnt[s], 2.f);
            }
        }
    } else {
        // distinct segs per half -> distinct shared addresses, race-free
        if ((unsigned)s < S_SH) {
            float4 a = acc4[s * 16 + q];
            a.x += s1a; a.y += s2a; a.z += s1b; a.w += s2b;
            acc4[s * 16 + q] = a;
            if (q == 0) cnt[s] += 1.f;           // lanes 0 and 16
        } else {
            global_fallback(s, s1a, s2a, s1b, s2b, q);
            if (q == 0 && (unsigned)s < S_MAX) atomicAdd(&g_cnt[s], 1.f);
        }
    }
}

__global__ void __launch_bounds__(W1 * 32, 2)
pass1_kernel(const float4* __restrict__ x4, const int* __restrict__ seg, int N) {
    float4* acc_all = (float4*)smem_raw;
    float*  cnt_all = (float*)(acc_all + W1 * ACC_F4_PER_WARP);

    const int warp = threadIdx.x >> 5;
    const int lane = threadIdx.x & 31;
    const int q    = lane & 15;       // float4 slot: channels 4q..4q+3
    const int h    = lane >> 4;       // row parity within pair

    for (int i = threadIdx.x; i < W1 * ACC_F4_PER_WARP; i += W1 * 32)
        acc_all[i] = make_float4(0.f, 0.f, 0.f, 0.f);
    for (int i = threadIdx.x; i < W1 * S_SH; i += W1 * 32)
        cnt_all[i] = 0.f;
    __syncthreads();

    float4* acc4 = acc_all + warp * ACC_F4_PER_WARP;
    float*  cnt  = cnt_all + warp * S_SH;

    const int P      = N >> 1;                      // row pairs
    const int nwarps = gridDim.x * W1;
    const int gw     = blockIdx.x * W1 + warp;
    const int L      = (P + nwarps - 1) / nwarps;   // contiguous pair chunk
    int pbeg = gw * L; if (pbeg > P) pbeg = P;
    int pend = pbeg + L; if (pend > P) pend = P;

    int p = pbeg;
    const int fit = pend - U1;
    if (p <= fit) {
        int sgA[U1]; float4 vA[U1];
#pragma unroll
        for (int j = 0; j < U1; j++) {
            int row = 2 * (p + j) + h;
            sgA[j] = __ldg(seg + row);
            vA[j]  = __ldcs(x4 + (size_t)row * 16 + q);
        }
        while (true) {
            int  nxt = p + U1;
            bool nv  = nxt <= fit;
            int sgB[U1]; float4 vB[U1];
            if (nv) {
#pragma unroll
                for (int j = 0; j < U1; j++) {
                    int row = 2 * (nxt + j) + h;
                    sgB[j] = __ldg(seg + row);
                    vB[j]  = __ldcs(x4 + (size_t)row * 16 + q);
                }
            }
#pragma unroll
            for (int j = 0; j < U1; j++)
                process_pair(acc4, cnt, lane, q, h, sgA[j], vA[j]);
            p = nxt;
            if (!nv) break;
#pragma unroll
            for (int j = 0; j < U1; j++) { sgA[j] = sgB[j]; vA[j] = vB[j]; }
        }
    }
    for (; p < pend; p++) {
        int    row = 2 * p + h;
        int    s   = __ldg(seg + row);
        float4 v   = __ldcs(x4 + (size_t)row * 16 + q);
        process_pair(acc4, cnt, lane, q, h, s, v);
    }

    // odd-N leftover row: global warp 0, float2 lanes (lane = group)
    if ((N & 1) && gw == 0) {
        int row = N - 1;
        int s   = __ldg(seg + row);
        const float2* x2 = (const float2*)x4;
        float2 v  = __ldg(x2 + (size_t)row * 32 + lane);
        float s1 = v.x + v.y;
        float s2 = fmaf(v.x, v.x, v.y * v.y);
        float2* acc2 = (float2*)acc4;
        if ((unsigned)s < S_SH) {
            float2 a = acc2[s * 32 + lane];
            a.x += s1; a.y += s2;
            acc2[s * 32 + lane] = a;
            if (lane == 0) cnt[s] += 1.f;
        } else if ((unsigned)s < S_MAX) {
            atomicAdd(&g_s12[s * G_ + lane].x, s1);
            atomicAdd(&g_s12[s * G_ + lane].y, s2);
            if (lane == 0) atomicAdd(&g_cnt[s], 1.f);
        }
    }
    __syncthreads();

    // reduce warp copies, push to global
    float2* acc2_all = (float2*)acc_all;          // [W1][S_SH*32] float2
    for (int i = threadIdx.x; i < S_SH * G_; i += W1 * 32) {
        float2 t = acc2_all[i];
#pragma unroll
        for (int w = 1; w < W1; w++) {
            float2 u = acc2_all[w * S_SH * G_ + i];
            t.x += u.x; t.y += u.y;
        }
        if (t.x != 0.f || t.y != 0.f) {
            atomicAdd(&g_s12[i].x, t.x);
            atomicAdd(&g_s12[i].y, t.y);
        }
    }
    for (int i = threadIdx.x; i < S_SH; i += W1 * 32) {
        float c = 0.f;
#pragma unroll
        for (int w = 0; w < W1; w++) c += cnt_all[w * S_SH + i];
        if (c != 0.f) atomicAdd(&g_cnt[i], c);
    }
}

// ---------------- k2: stats ----------------
__global__ void stats_kernel() {
    int i = blockIdx.x * blockDim.x + threadIdx.x;
    if (i >= S_MAX * G_) return;
    int   s    = i >> 5;                         // / G_
    float n    = fmaxf(g_cnt[s] * 2.f, 1.f);     // elements = rows * Cg, guarded
    float2 t   = g_s12[i];
    float mean = t.x / n;
    float var  = t.y / n - mean * mean;
    float inv  = rsqrtf(var + EPS_);
    g_stat[i]  = make_float2(mean, inv);
}

// ---------------- k3: normalize (float4, warp = 2 rows/step) ----------------
#define U3 4

__global__ void __launch_bounds__(256)
pass3_kernel(const float4* __restrict__ x4, const int* __restrict__ seg,
             const float* __restrict__ gamma, const float* __restrict__ beta,
             float4* __restrict__ out4, int N) {
    const int lane = threadIdx.x & 31;
    const int q    = lane & 15;       // float4 slot within row: channels 4q..4q+3
    const int h    = lane >> 4;       // row parity within pair

    const float4 gm = __ldg((const float4*)gamma + q);
    const float4 bt = __ldg((const float4*)beta  + q);
    const float4* stat4 = (const float4*)g_stat;   // [s*16+q] = (m2q,i2q,m2q1,i2q1)

    const int P      = N >> 1;                     // row pairs
    const int nwarps = (gridDim.x * 256) >> 5;
    const int gw     = (blockIdx.x * 256 + threadIdx.x) >> 5;
    const int L      = (P + nwarps - 1) / nwarps;  // contiguous pair chunk
    int pbeg = gw * L; if (pbeg > P) pbeg = P;
    int pend = pbeg + L; if (pend > P) pend = P;

    int p = pbeg;
    for (; p + U3 <= pend; p += U3) {
        int sg[U3]; float4 v[U3];
#pragma unroll
        for (int j = 0; j < U3; j++) {
            int row = 2 * (p + j) + h;
            int s   = __ldg(seg + row);
            sg[j]   = min(max(s, 0), S_MAX - 1);
            v[j]    = __ldcs(x4 + (size_t)row * 16 + q);
        }
        float4 st[U3];
#pragma unroll
        for (int j = 0; j < U3; j++)
            st[j] = __ldg(stat4 + sg[j] * 16 + q);
#pragma unroll
        for (int j = 0; j < U3; j++) {
            int row = 2 * (p + j) + h;
            float4 o;
            o.x = fmaf((v[j].x - st[j].x) * st[j].y, gm.x, bt.x);
            o.y = fmaf((v[j].y - st[j].x) * st[j].y, gm.y, bt.y);
            o.z = fmaf((v[j].z - st[j].z) * st[j].w, gm.z, bt.z);
            o.w = fmaf((v[j].w - st[j].z) * st[j].w, gm.w, bt.w);
            __stcs(out4 + (size_t)row * 16 + q, o);
        }
    }
    for (; p < pend; p++) {
        int row = 2 * p + h;
        int s   = min(max(__ldg(seg + row), 0), S_MAX - 1);
        float4 v  = __ldcs(x4 + (size_t)row * 16 + q);
        float4 st = __ldg(stat4 + s * 16 + q);
        float4 o;
        o.x = fmaf((v.x - st.x) * st.y, gm.x, bt.x);
        o.y = fmaf((v.y - st.x) * st.y, gm.y, bt.y);
        o.z = fmaf((v.z - st.z) * st.w, gm.z, bt.z);
        o.w = fmaf((v.w - st.z) * st.w, gm.w, bt.w);
        __stcs(out4 + (size_t)row * 16 + q, o);
    }
    // odd-N tail row
    if ((N & 1) && gw == 0) {
        int row = N - 1;
        int s   = min(max(__ldg(seg + row), 0), S_MAX - 1);
        const float2* x2 = (const float2*)x4;
        float2 v  = __ldg(x2 + (size_t)row * 32 + lane);
        float2 st = g_stat[s * 32 + lane];
        const float2 gm2 = __ldg((const float2*)gamma + lane);
        const float2 bt2 = __ldg((const float2*)beta  + lane);
        float2 o;
        o.x = fmaf((v.x - st.x) * st.y, gm2.x, bt2.x);
        o.y = fmaf((v.y - st.x) * st.y, gm2.y, bt2.y);
        ((float2*)out4)[(size_t)row * 32 + lane] = o;
    }
}

// ---------------- launch ----------------
extern "C" void kernel_launch(void* const* d_in, const int* in_sizes, int n_in,
                              void* d_out, int out_size) {
    const float* features = (const float*)d_in[0];
    const float* gamma    = (const float*)d_in[1];
    const float* beta     = (const float*)d_in[2];
    const int*   seg      = (const int*)d_in[3];
    // d_in[4] = num_instances (device scalar) — unused; scratch sized to S_MAX.

    const int N = in_sizes[0] / C_;

    const size_t smem1 = (size_t)W1 * ACC_F4_PER_WARP * sizeof(float4)
                       + (size_t)W1 * S_SH * sizeof(float);   // 108160 B
    cudaFuncSetAttribute(pass1_kernel,
                         cudaFuncAttributeMaxDynamicSharedMemorySize, (int)smem1);

    zero_kernel<<<(S_MAX * G_ + 255) / 256, 256>>>();
    pass1_kernel<<<296, W1 * 32, smem1>>>((const float4*)features, seg, N);
    stats_kernel<<<(S_MAX * G_ + 255) / 256, 256>>>();
    pass3_kernel<<<1184, 256>>>((const float4*)features, seg, gamma, beta,
                                (float4*)d_out, N);
}